// round 12
// baseline (speedup 1.0000x reference)
#include <cuda_runtime.h>
#include <math.h>

#define BB 32
#define NN 128
#define EE 16384
#define ETOT (BB*EE)
#define DD 72
#define HH 72
#define BN (BB*NN)

// ---------------- device scratch ----------------
__device__ float  g_P[BN*HH];
__device__ float  g_Q[BN*HH];
__device__ double g_esum[HH];
__device__ double g_esq[HH];
__device__ float  g_bn_e[2*HH];
__device__ float  g_magg[BN*HH];
__device__ float  g_agg[BN*4];
__device__ int    g_cnt[BN];
__device__ float  g_z2[BN*HH];
__device__ float  g_bn_h[2*HH];

__device__ __forceinline__ float psi_f(float p) {
    return copysignf(log1pf(fabsf(p)), p);
}

// packed fp32 helpers (FFMA2 path — PTX-only)
__device__ __forceinline__ unsigned long long pack2(float v) {
    unsigned long long r;
    asm("mov.b64 %0, {%1, %1};" : "=l"(r) : "f"(v));
    return r;
}
__device__ __forceinline__ void fma2(unsigned long long& d,
                                     unsigned long long a, unsigned long long b) {
    asm("fma.rn.f32x2 %0, %1, %2, %0;" : "+l"(d) : "l"(a), "l"(b));
}
__device__ __forceinline__ void unpack2(unsigned long long v, float& lo, float& hi) {
    asm("mov.b64 {%0, %1}, %2;" : "=f"(lo), "=f"(hi) : "l"(v));
}

// ---- per-node P,Q = h @ We1[:144]; also zero-init accumulators ----
__global__ void __launch_bounds__(128) k_pre(
    const float* __restrict__ h, const float* __restrict__ We1)
{
    __shared__ float sW[144*72];
    int tid = threadIdx.x;
    int gid = blockIdx.x * 128 + tid;      // 0..4095

    // fold former k_zero here (disjoint arrays; stream order covers k_stats)
    for (int t = gid; t < BN*HH; t += BN) g_magg[t] = 0.f;
    for (int t = gid; t < BN*4;  t += BN) g_agg[t]  = 0.f;
    g_cnt[gid] = 0;
    if (gid < HH) { g_esum[gid] = 0.0; g_esq[gid] = 0.0; }

    for (int t = tid; t < 144*72; t += 128) sW[t] = We1[t];
    __syncthreads();

    int bn = gid;
    float hv[72];
    for (int k = 0; k < 72; k++) hv[k] = h[bn*72 + k];
    float* Pr = g_P + bn*72;
    float* Qr = g_Q + bn*72;
    for (int jc = 0; jc < 72; jc++) {
        float a = 0.f, b2 = 0.f;
        for (int k = 0; k < 72; k++) {
            a  += hv[k] * sW[k*72 + jc];
            b2 += hv[k] * sW[(72+k)*72 + jc];
        }
        Pr[jc] = a;
        Qr[jc] = b2;
    }
}

// ---- BN stats, channel-parallel: 4 edge-groups x 72 channels ----
__global__ void __launch_bounds__(288) k_stats(
    const float* __restrict__ x,
    const int* __restrict__ ei, const int* __restrict__ ej,
    const float* __restrict__ We1)
{
    __shared__ float snv[256], sdv[256];
    __shared__ int   si[256], sj[256];
    __shared__ float ssum[72], ssq[72];
    int tid = threadIdx.x;
    int g = tid / 72;
    int c = tid - g*72;
    if (tid < 72) { ssum[tid] = 0.f; ssq[tid] = 0.f; }
    float w1 = We1[144*72 + c];
    float w2 = We1[145*72 + c];

    int b = blockIdx.x >> 3;
    float s = 0.f, q = 0.f;

    #pragma unroll 1
    for (int t = 0; t < 8; t++) {
        __syncthreads();
        if (tid < 256) {
            int eg = blockIdx.x*2048 + t*256 + tid;
            int i = ei[eg], j = ej[eg];
            atomicAdd(&g_cnt[b*NN + i], 1);
            si[tid] = i; sj[tid] = j;
            const float* xi = x + (b*NN + i)*4;
            const float* xj = x + (b*NN + j)*4;
            float d0 = xi[0]-xj[0], d1 = xi[1]-xj[1], d2 = xi[2]-xj[2], d3 = xi[3]-xj[3];
            snv[tid] = psi_f(d0*d0 - d1*d1 - d2*d2 - d3*d3);
            sdv[tid] = psi_f(xi[0]*xj[0] - xi[1]*xj[1] - xi[2]*xj[2] - xi[3]*xj[3]);
        }
        __syncthreads();
        int e0 = g * 64;
        #pragma unroll 4
        for (int e = e0; e < e0 + 64; e++) {
            float v = g_P[(size_t)(b*NN + si[e])*72 + c]
                    + g_Q[(size_t)(b*NN + sj[e])*72 + c]
                    + snv[e]*w1 + sdv[e]*w2;
            s += v; q += v*v;
        }
    }
    atomicAdd(&ssum[c], s);
    atomicAdd(&ssq[c], q);
    __syncthreads();
    if (tid < 72) {
        atomicAdd(&g_esum[tid], (double)ssum[tid]);
        atomicAdd(&g_esq[tid],  (double)ssq[tid]);
    }
}

__global__ void k_fin_e(const float* __restrict__ g1, const float* __restrict__ b1) {
    int c = threadIdx.x;
    if (c < 72) {
        double inv = 1.0 / (double)ETOT;
        double mu  = g_esum[c] * inv;
        double var = g_esq[c] * inv - mu*mu;
        float a = g1[c] * (float)(1.0 / sqrt(var + 1e-5));
        g_bn_e[c] = a;
        g_bn_e[72 + c] = b1[c] - (float)mu * a;
    }
}

// ---- main edge kernel: 128 edges/block, block GEMMs (FFMA2) ----
#define SM_W2   0
#define SM_WX   5184
#define SM_ZT   10368
#define SM_VEC  19872
#define SM_MDOT 20448
#define SM_GATE 20576
#define SM_SI   20704
#define SM_SJ   20832
#define SM_TOT  20960   /* floats -> 83840 bytes */

__global__ void __launch_bounds__(256) k_m(
    const float* __restrict__ x,
    const int* __restrict__ ei, const int* __restrict__ ej,
    const float* __restrict__ We1, const float* __restrict__ We2,
    const float* __restrict__ be2, const float* __restrict__ Wm,
    const float* __restrict__ bm, const float* __restrict__ Wx1,
    const float* __restrict__ bx1, const float* __restrict__ Wx2,
    float* __restrict__ out_m)
{
    extern __shared__ float sm[];
    float* sW2   = sm + SM_W2;
    float* sWx   = sm + SM_WX;
    float* szt   = sm + SM_ZT;
    float* svec  = sm + SM_VEC;
    float* smdot = sm + SM_MDOT;
    float* sgate = sm + SM_GATE;
    int*   si    = (int*)(sm + SM_SI);
    int*   sj    = (int*)(sm + SM_SJ);

    const int tid = threadIdx.x;
    const int blk = blockIdx.x;
    const int b   = blk >> 7;

    for (int t = tid; t < 5184; t += 256) { sW2[t] = We2[t]; sWx[t] = Wx1[t]; }
    if (tid < 72) {
        svec[tid]        = g_bn_e[tid];
        svec[72  + tid]  = g_bn_e[72 + tid];
        svec[144 + tid]  = We1[144*72 + tid];
        svec[216 + tid]  = We1[145*72 + tid];
        svec[288 + tid]  = be2[tid];
        svec[360 + tid]  = Wm[tid];
        svec[432 + tid]  = bx1[tid];
        svec[504 + tid]  = Wx2[tid];
    }
    if (tid < 128) {
        int eg = blk*128 + tid;
        si[tid] = ei[eg];
        sj[tid] = ej[eg];
        smdot[tid] = bm[0];
        sgate[tid] = 0.f;
    }
    __syncthreads();

    // phase A: zb = relu(BN(z1)) into szt (transposed), float4 gathers
    {
        int e = tid >> 1, half = tid & 1, c0 = half*36;
        int i = si[e], j = sj[e];
        const float* xi = x + (b*NN + i)*4;
        const float* xj = x + (b*NN + j)*4;
        float d0 = xi[0]-xj[0], d1 = xi[1]-xj[1], d2 = xi[2]-xj[2], d3 = xi[3]-xj[3];
        float nv = psi_f(d0*d0 - d1*d1 - d2*d2 - d3*d3);
        float dv = psi_f(xi[0]*xj[0] - xi[1]*xj[1] - xi[2]*xj[2] - xi[3]*xj[3]);
        const float4* Pr = (const float4*)(g_P + (size_t)(b*NN + i)*72 + c0);
        const float4* Qr = (const float4*)(g_Q + (size_t)(b*NN + j)*72 + c0);
        #pragma unroll
        for (int c4 = 0; c4 < 9; c4++) {
            float4 p = Pr[c4];
            float4 q = Qr[c4];
            int cc = c0 + c4*4;
            float v0 = p.x + q.x + nv*svec[144+cc+0] + dv*svec[216+cc+0];
            float v1 = p.y + q.y + nv*svec[144+cc+1] + dv*svec[216+cc+1];
            float v2 = p.z + q.z + nv*svec[144+cc+2] + dv*svec[216+cc+2];
            float v3 = p.w + q.w + nv*svec[144+cc+3] + dv*svec[216+cc+3];
            szt[(cc+0)*132 + e] = fmaxf(fmaf(v0, svec[cc+0], svec[72+cc+0]), 0.f);
            szt[(cc+1)*132 + e] = fmaxf(fmaf(v1, svec[cc+1], svec[72+cc+1]), 0.f);
            szt[(cc+2)*132 + e] = fmaxf(fmaf(v2, svec[cc+2], svec[72+cc+2]), 0.f);
            szt[(cc+3)*132 + e] = fmaxf(fmaf(v3, svec[cc+3], svec[72+cc+3]), 0.f);
        }
    }
    __syncthreads();

    const int egrp = tid >> 3;
    const int jo   = (tid & 7) * 9;
    const int e0   = egrp * 4;

    // phase B: GEMM1 with packed f32x2 (edge pairs)
    unsigned long long a01[9], a23[9];
    #pragma unroll
    for (int jj = 0; jj < 9; jj++) {
        unsigned long long bv = pack2(svec[288 + jo + jj]);
        a01[jj] = bv; a23[jj] = bv;
    }
    #pragma unroll 4
    for (int k = 0; k < 72; k++) {
        ulonglong2 zp = *(const ulonglong2*)&szt[k*132 + e0];
        #pragma unroll
        for (int jj = 0; jj < 9; jj++) {
            unsigned long long wp = pack2(sW2[k*72 + jo + jj]);
            fma2(a01[jj], zp.x, wp);
            fma2(a23[jj], zp.y, wp);
        }
    }
    float acc[36];
    #pragma unroll
    for (int jj = 0; jj < 9; jj++) {
        unpack2(a01[jj], acc[jj],    acc[9+jj]);
        unpack2(a23[jj], acc[18+jj], acc[27+jj]);
    }

    // phase C: relu + partial mdot
    #pragma unroll
    for (int i = 0; i < 4; i++) {
        float pd = 0.f;
        #pragma unroll
        for (int jj = 0; jj < 9; jj++) {
            float v = fmaxf(acc[i*9 + jj], 0.f);
            acc[i*9 + jj] = v;
            pd = fmaf(v, svec[360 + jo + jj], pd);
        }
        atomicAdd(&smdot[e0 + i], pd);
    }
    __syncthreads();

    // phase D: sigmoid scale, m0 -> szt + global magg
    #pragma unroll
    for (int i = 0; i < 4; i++) {
        float sg = 1.f / (1.f + expf(-smdot[e0 + i]));
        #pragma unroll
        for (int jj = 0; jj < 9; jj++) acc[i*9 + jj] *= sg;
    }
    #pragma unroll
    for (int jj = 0; jj < 9; jj++) {
        float4 v4 = make_float4(acc[jj], acc[9+jj], acc[18+jj], acc[27+jj]);
        *(float4*)&szt[(jo + jj)*132 + e0] = v4;
    }
    #pragma unroll
    for (int i = 0; i < 4; i++) {
        float* ma = g_magg + (size_t)(b*NN + si[e0 + i])*72 + jo;
        #pragma unroll
        for (int jj = 0; jj < 9; jj++) atomicAdd(ma + jj, acc[i*9 + jj]);
    }
    __syncthreads();

    // phase E: coalesced m output
    {
        float* mo = out_m + (size_t)blk * (128*72);
        for (int t = tid; t < 128*72; t += 256) {
            int e = t / 72, c = t - e*72;
            mo[t] = szt[c*132 + e];
        }
    }

    // phase F: GEMM2 with packed f32x2 -> gate
    unsigned long long b01[9], b23[9];
    #pragma unroll
    for (int jj = 0; jj < 9; jj++) {
        unsigned long long bv = pack2(svec[432 + jo + jj]);
        b01[jj] = bv; b23[jj] = bv;
    }
    #pragma unroll 4
    for (int k = 0; k < 72; k++) {
        ulonglong2 zp = *(const ulonglong2*)&szt[k*132 + e0];
        #pragma unroll
        for (int jj = 0; jj < 9; jj++) {
            unsigned long long wp = pack2(sWx[k*72 + jo + jj]);
            fma2(b01[jj], zp.x, wp);
            fma2(b23[jj], zp.y, wp);
        }
    }
    float acc2[36];
    #pragma unroll
    for (int jj = 0; jj < 9; jj++) {
        unpack2(b01[jj], acc2[jj],    acc2[9+jj]);
        unpack2(b23[jj], acc2[18+jj], acc2[27+jj]);
    }
    #pragma unroll
    for (int i = 0; i < 4; i++) {
        float pg = 0.f;
        #pragma unroll
        for (int jj = 0; jj < 9; jj++)
            pg = fmaf(fmaxf(acc2[i*9 + jj], 0.f), svec[504 + jo + jj], pg);
        atomicAdd(&sgate[e0 + i], pg);
    }
    __syncthreads();

    // phase G: x-path atomics
    if (tid < 128) {
        int e = tid;
        int i = si[e], j = sj[e];
        float gate = sgate[e];
        const float* xi = x + (b*NN + i)*4;
        const float* xj = x + (b*NN + j)*4;
        float* ag = g_agg + (size_t)(b*NN + i)*4;
        #pragma unroll
        for (int d = 0; d < 4; d++) {
            float diff = xi[d] - xj[d];
            atomicAdd(ag + d, fminf(fmaxf(diff*gate, -100.f), 100.f));
        }
    }
}

// ---- node MLP pre-BN: block GEMM (128 nodes/block, K=148) ----
__global__ void __launch_bounds__(256) k_node_h1(
    const float* __restrict__ h, const float* __restrict__ na,
    const float* __restrict__ Wh1, const float* __restrict__ bh1)
{
    extern __shared__ float smh[];
    float* sW    = smh;
    float* sin_t = smh + 10656;
    int tid = threadIdx.x;
    int blk = blockIdx.x;

    for (int t = tid; t < 10656; t += 256) sW[t] = Wh1[t];
    for (int idx = tid; idx < 148*128; idx += 256) {
        int k = idx >> 7, n = idx & 127;
        int bn = blk*128 + n;
        float v;
        if (k < 72)       v = h[bn*72 + k];
        else if (k < 144) v = g_magg[bn*72 + (k-72)];
        else              v = na[bn*4 + (k-144)];
        sin_t[k*132 + n] = v;
    }
    __syncthreads();

    const int egrp = tid >> 3;
    const int jo   = (tid & 7) * 9;
    const int e0   = egrp * 4;

    float acc[36];
    #pragma unroll
    for (int jj = 0; jj < 9; jj++) {
        float bv = __ldg(bh1 + jo + jj);
        acc[jj] = bv; acc[9+jj] = bv; acc[18+jj] = bv; acc[27+jj] = bv;
    }
    #pragma unroll 4
    for (int k = 0; k < 148; k++) {
        float4 zv = *(const float4*)&sin_t[k*132 + e0];
        #pragma unroll
        for (int jj = 0; jj < 9; jj++) {
            float w = sW[k*72 + jo + jj];
            acc[jj]    = fmaf(zv.x, w, acc[jj]);
            acc[9+jj]  = fmaf(zv.y, w, acc[9+jj]);
            acc[18+jj] = fmaf(zv.z, w, acc[18+jj]);
            acc[27+jj] = fmaf(zv.w, w, acc[27+jj]);
        }
    }
    #pragma unroll
    for (int i = 0; i < 4; i++) {
        float* zr = g_z2 + (size_t)(blk*128 + e0 + i)*72 + jo;
        #pragma unroll
        for (int jj = 0; jj < 9; jj++) zr[jj] = acc[i*9 + jj];
    }
}

__global__ void k_fin_h(const float* __restrict__ gh, const float* __restrict__ bh) {
    int c = blockIdx.x;
    int tid = threadIdx.x;
    double s = 0.0, q = 0.0;
    for (int r = tid; r < BN; r += 128) {
        double v = (double)g_z2[r*72 + c];
        s += v; q += v*v;
    }
    __shared__ double rs[128], rq[128];
    rs[tid] = s; rq[tid] = q;
    __syncthreads();
    for (int off = 64; off > 0; off >>= 1) {
        if (tid < off) { rs[tid] += rs[tid+off]; rq[tid] += rq[tid+off]; }
        __syncthreads();
    }
    if (tid == 0) {
        double mu = rs[0] / (double)BN;
        double var = rq[0] / (double)BN - mu*mu;
        float a = gh[c] * (float)(1.0 / sqrt(var + 1e-5));
        g_bn_h[c] = a;
        g_bn_h[72 + c] = bh[c] - (float)mu * a;
    }
}

// ---- node output: block GEMM (128 nodes/block, K=72) + x_out ----
__global__ void __launch_bounds__(256) k_node_h2(
    const float* __restrict__ h, const float* __restrict__ x,
    const float* __restrict__ Wh2, const float* __restrict__ bh2,
    float* __restrict__ out)
{
    extern __shared__ float smh[];
    float* sW   = smh;
    float* sv_t = smh + 5184;
    float* sbn  = smh + 14688;
    int tid = threadIdx.x;
    int blk = blockIdx.x;

    for (int t = tid; t < 5184; t += 256) sW[t] = Wh2[t];
    if (tid < 144) sbn[tid] = g_bn_h[tid];
    __syncthreads();
    for (int idx = tid; idx < 72*128; idx += 256) {
        int c = idx >> 7, n = idx & 127;
        float v = g_z2[(size_t)(blk*128 + n)*72 + c];
        sv_t[c*132 + n] = fmaxf(fmaf(v, sbn[c], sbn[72 + c]), 0.f);
    }
    __syncthreads();

    const int egrp = tid >> 3;
    const int jo   = (tid & 7) * 9;
    const int e0   = egrp * 4;

    float acc[36];
    #pragma unroll
    for (int jj = 0; jj < 9; jj++) {
        float bv = __ldg(bh2 + jo + jj);
        acc[jj] = bv; acc[9+jj] = bv; acc[18+jj] = bv; acc[27+jj] = bv;
    }
    #pragma unroll 4
    for (int k = 0; k < 72; k++) {
        float4 zv = *(const float4*)&sv_t[k*132 + e0];
        #pragma unroll
        for (int jj = 0; jj < 9; jj++) {
            float w = sW[k*72 + jo + jj];
            acc[jj]    = fmaf(zv.x, w, acc[jj]);
            acc[9+jj]  = fmaf(zv.y, w, acc[9+jj]);
            acc[18+jj] = fmaf(zv.z, w, acc[18+jj]);
            acc[27+jj] = fmaf(zv.w, w, acc[27+jj]);
        }
    }
    #pragma unroll
    for (int i = 0; i < 4; i++) {
        int bn = blk*128 + e0 + i;
        const float* hr = h + (size_t)bn*72 + jo;
        float* oh = out + (size_t)bn*72 + jo;
        #pragma unroll
        for (int jj = 0; jj < 9; jj++) oh[jj] = hr[jj] + acc[i*9 + jj];
    }

    if (tid < 128) {
        int bn = blk*128 + tid;
        float cn = fmaxf((float)g_cnt[bn], 1.f);
        float inv = 1.f / cn;
        float* ox = out + BN*HH + (size_t)bn*4;
        #pragma unroll
        for (int d = 0; d < 4; d++)
            ox[d] = x[bn*4 + d] + g_agg[bn*4 + d] * inv;
    }
}

extern "C" void kernel_launch(void* const* d_in, const int* in_sizes, int n_in,
                              void* d_out, int out_size)
{
    (void)in_sizes; (void)n_in; (void)out_size;
    const float* h   = (const float*)d_in[0];
    const float* x   = (const float*)d_in[1];
    const int*   ei  = (const int*)  d_in[2];
    const int*   ej  = (const int*)  d_in[3];
    const float* na  = (const float*)d_in[4];
    const float* We1 = (const float*)d_in[5];
    const float* g1  = (const float*)d_in[6];
    const float* b1  = (const float*)d_in[7];
    const float* We2 = (const float*)d_in[8];
    const float* be2 = (const float*)d_in[9];
    const float* Wm  = (const float*)d_in[10];
    const float* bm  = (const float*)d_in[11];
    const float* Wx1 = (const float*)d_in[12];
    const float* bx1 = (const float*)d_in[13];
    const float* Wx2 = (const float*)d_in[14];
    const float* Wh1 = (const float*)d_in[15];
    const float* bh1 = (const float*)d_in[16];
    const float* gh  = (const float*)d_in[17];
    const float* bhv = (const float*)d_in[18];
    const float* Wh2 = (const float*)d_in[19];
    const float* bh2 = (const float*)d_in[20];

    float* out = (float*)d_out;
    float* out_m = out + BN*HH + BN*4;

    cudaFuncSetAttribute(k_m, cudaFuncAttributeMaxDynamicSharedMemorySize,
                         SM_TOT * (int)sizeof(float));
    cudaFuncSetAttribute(k_node_h1, cudaFuncAttributeMaxDynamicSharedMemorySize,
                         30192 * (int)sizeof(float));
    cudaFuncSetAttribute(k_node_h2, cudaFuncAttributeMaxDynamicSharedMemorySize,
                         14832 * (int)sizeof(float));

    k_pre<<<BB, 128>>>(h, We1);                         // launch 1 (includes zeroing)
    k_stats<<<256, 288>>>(x, ei, ej, We1);              // launch 2
    k_fin_e<<<1, 72>>>(g1, b1);                         // launch 3
    k_m<<<ETOT/128, 256, SM_TOT*(int)sizeof(float)>>>(  // launch 4  <-- profile slot
        x, ei, ej, We1, We2, be2, Wm, bm, Wx1, bx1, Wx2, out_m);
    k_node_h1<<<BB, 256, 30192*(int)sizeof(float)>>>(h, na, Wh1, bh1);
    k_fin_h<<<72, 128>>>(gh, bhv);
    k_node_h2<<<BB, 256, 14832*(int)sizeof(float)>>>(h, x, Wh2, bh2, out);
}

// round 13
// speedup vs baseline: 1.0024x; 1.0024x over previous
#include <cuda_runtime.h>
#include <math.h>

#define BB 32
#define NN 128
#define EE 16384
#define ETOT (BB*EE)
#define DD 72
#define HH 72
#define BN (BB*NN)

// ---------------- device scratch ----------------
__device__ float  g_P[BN*HH];
__device__ float  g_Q[BN*HH];
__device__ double g_esum[HH];
__device__ double g_esq[HH];
__device__ float  g_bn_e[2*HH];
__device__ float  g_magg[BN*HH];
__device__ float  g_agg[BN*4];
__device__ int    g_cnt[BN];
__device__ float  g_z2[BN*HH];
__device__ float  g_bn_h[2*HH];

__device__ __forceinline__ float psi_f(float p) {
    return copysignf(log1pf(fabsf(p)), p);
}

// packed fp32 helpers (FFMA2 path — PTX-only)
__device__ __forceinline__ unsigned long long pack2(float v) {
    unsigned long long r;
    asm("mov.b64 %0, {%1, %1};" : "=l"(r) : "f"(v));
    return r;
}
__device__ __forceinline__ void fma2(unsigned long long& d,
                                     unsigned long long a, unsigned long long b) {
    asm("fma.rn.f32x2 %0, %1, %2, %0;" : "+l"(d) : "l"(a), "l"(b));
}
__device__ __forceinline__ void unpack2(unsigned long long v, float& lo, float& hi) {
    asm("mov.b64 {%0, %1}, %2;" : "=f"(lo), "=f"(hi) : "l"(v));
}

// ---- per-node P,Q = h @ We1[:144]; also zero-init accumulators ----
__global__ void __launch_bounds__(128) k_pre(
    const float* __restrict__ h, const float* __restrict__ We1)
{
    __shared__ float sW[144*72];
    int tid = threadIdx.x;
    int gid = blockIdx.x * 128 + tid;      // 0..4095

    // fold former k_zero here (disjoint arrays; stream order covers k_stats)
    for (int t = gid; t < BN*HH; t += BN) g_magg[t] = 0.f;
    for (int t = gid; t < BN*4;  t += BN) g_agg[t]  = 0.f;
    g_cnt[gid] = 0;
    if (gid < HH) { g_esum[gid] = 0.0; g_esq[gid] = 0.0; }

    for (int t = tid; t < 144*72; t += 128) sW[t] = We1[t];
    __syncthreads();

    int bn = gid;
    float hv[72];
    for (int k = 0; k < 72; k++) hv[k] = h[bn*72 + k];
    float* Pr = g_P + bn*72;
    float* Qr = g_Q + bn*72;
    for (int jc = 0; jc < 72; jc++) {
        float a = 0.f, b2 = 0.f;
        for (int k = 0; k < 72; k++) {
            a  += hv[k] * sW[k*72 + jc];
            b2 += hv[k] * sW[(72+k)*72 + jc];
        }
        Pr[jc] = a;
        Qr[jc] = b2;
    }
}

// ---- BN stats, channel-parallel: 4 edge-groups x 72 channels ----
__global__ void __launch_bounds__(288) k_stats(
    const float* __restrict__ x,
    const int* __restrict__ ei, const int* __restrict__ ej,
    const float* __restrict__ We1)
{
    __shared__ float snv[256], sdv[256];
    __shared__ int   si[256], sj[256];
    __shared__ float ssum[72], ssq[72];
    int tid = threadIdx.x;
    int g = tid / 72;
    int c = tid - g*72;
    if (tid < 72) { ssum[tid] = 0.f; ssq[tid] = 0.f; }
    float w1 = We1[144*72 + c];
    float w2 = We1[145*72 + c];

    int b = blockIdx.x >> 3;
    float s = 0.f, q = 0.f;

    #pragma unroll 1
    for (int t = 0; t < 8; t++) {
        __syncthreads();
        if (tid < 256) {
            int eg = blockIdx.x*2048 + t*256 + tid;
            int i = ei[eg], j = ej[eg];
            atomicAdd(&g_cnt[b*NN + i], 1);
            si[tid] = i; sj[tid] = j;
            const float* xi = x + (b*NN + i)*4;
            const float* xj = x + (b*NN + j)*4;
            float d0 = xi[0]-xj[0], d1 = xi[1]-xj[1], d2 = xi[2]-xj[2], d3 = xi[3]-xj[3];
            snv[tid] = psi_f(d0*d0 - d1*d1 - d2*d2 - d3*d3);
            sdv[tid] = psi_f(xi[0]*xj[0] - xi[1]*xj[1] - xi[2]*xj[2] - xi[3]*xj[3]);
        }
        __syncthreads();
        int e0 = g * 64;
        #pragma unroll 4
        for (int e = e0; e < e0 + 64; e++) {
            float v = g_P[(size_t)(b*NN + si[e])*72 + c]
                    + g_Q[(size_t)(b*NN + sj[e])*72 + c]
                    + snv[e]*w1 + sdv[e]*w2;
            s += v; q += v*v;
        }
    }
    atomicAdd(&ssum[c], s);
    atomicAdd(&ssq[c], q);
    __syncthreads();
    if (tid < 72) {
        atomicAdd(&g_esum[tid], (double)ssum[tid]);
        atomicAdd(&g_esq[tid],  (double)ssq[tid]);
    }
}

__global__ void k_fin_e(const float* __restrict__ g1, const float* __restrict__ b1) {
    int c = threadIdx.x;
    if (c < 72) {
        double inv = 1.0 / (double)ETOT;
        double mu  = g_esum[c] * inv;
        double var = g_esq[c] * inv - mu*mu;
        float a = g1[c] * (float)(1.0 / sqrt(var + 1e-5));
        g_bn_e[c] = a;
        g_bn_e[72 + c] = b1[c] - (float)mu * a;
    }
}

// ---- main edge kernel: 128 edges/block, block GEMMs (FFMA2) ----
#define SM_W2   0
#define SM_WX   5184
#define SM_ZT   10368
#define SM_VEC  19872
#define SM_MDOT 20448
#define SM_GATE 20576
#define SM_SI   20704
#define SM_SJ   20832
#define SM_TOT  20960   /* floats -> 83840 bytes */

__global__ void __launch_bounds__(256) k_m(
    const float* __restrict__ x,
    const int* __restrict__ ei, const int* __restrict__ ej,
    const float* __restrict__ We1, const float* __restrict__ We2,
    const float* __restrict__ be2, const float* __restrict__ Wm,
    const float* __restrict__ bm, const float* __restrict__ Wx1,
    const float* __restrict__ bx1, const float* __restrict__ Wx2,
    float* __restrict__ out_m)
{
    extern __shared__ float sm[];
    float* sW2   = sm + SM_W2;
    float* sWx   = sm + SM_WX;
    float* szt   = sm + SM_ZT;
    float* svec  = sm + SM_VEC;
    float* smdot = sm + SM_MDOT;
    float* sgate = sm + SM_GATE;
    int*   si    = (int*)(sm + SM_SI);
    int*   sj    = (int*)(sm + SM_SJ);

    const int tid = threadIdx.x;
    const int blk = blockIdx.x;
    const int b   = blk >> 7;

    for (int t = tid; t < 5184; t += 256) { sW2[t] = We2[t]; sWx[t] = Wx1[t]; }
    if (tid < 72) {
        svec[tid]        = g_bn_e[tid];
        svec[72  + tid]  = g_bn_e[72 + tid];
        svec[144 + tid]  = We1[144*72 + tid];
        svec[216 + tid]  = We1[145*72 + tid];
        svec[288 + tid]  = be2[tid];
        svec[360 + tid]  = Wm[tid];
        svec[432 + tid]  = bx1[tid];
        svec[504 + tid]  = Wx2[tid];
    }
    if (tid < 128) {
        int eg = blk*128 + tid;
        si[tid] = ei[eg];
        sj[tid] = ej[eg];
        smdot[tid] = bm[0];
        sgate[tid] = 0.f;
    }
    __syncthreads();

    // phase A: zb = relu(BN(z1)) into szt (transposed), float4 gathers
    {
        int e = tid >> 1, half = tid & 1, c0 = half*36;
        int i = si[e], j = sj[e];
        const float* xi = x + (b*NN + i)*4;
        const float* xj = x + (b*NN + j)*4;
        float d0 = xi[0]-xj[0], d1 = xi[1]-xj[1], d2 = xi[2]-xj[2], d3 = xi[3]-xj[3];
        float nv = psi_f(d0*d0 - d1*d1 - d2*d2 - d3*d3);
        float dv = psi_f(xi[0]*xj[0] - xi[1]*xj[1] - xi[2]*xj[2] - xi[3]*xj[3]);
        const float4* Pr = (const float4*)(g_P + (size_t)(b*NN + i)*72 + c0);
        const float4* Qr = (const float4*)(g_Q + (size_t)(b*NN + j)*72 + c0);
        #pragma unroll
        for (int c4 = 0; c4 < 9; c4++) {
            float4 p = Pr[c4];
            float4 q = Qr[c4];
            int cc = c0 + c4*4;
            float v0 = p.x + q.x + nv*svec[144+cc+0] + dv*svec[216+cc+0];
            float v1 = p.y + q.y + nv*svec[144+cc+1] + dv*svec[216+cc+1];
            float v2 = p.z + q.z + nv*svec[144+cc+2] + dv*svec[216+cc+2];
            float v3 = p.w + q.w + nv*svec[144+cc+3] + dv*svec[216+cc+3];
            szt[(cc+0)*132 + e] = fmaxf(fmaf(v0, svec[cc+0], svec[72+cc+0]), 0.f);
            szt[(cc+1)*132 + e] = fmaxf(fmaf(v1, svec[cc+1], svec[72+cc+1]), 0.f);
            szt[(cc+2)*132 + e] = fmaxf(fmaf(v2, svec[cc+2], svec[72+cc+2]), 0.f);
            szt[(cc+3)*132 + e] = fmaxf(fmaf(v3, svec[cc+3], svec[72+cc+3]), 0.f);
        }
    }
    __syncthreads();

    const int egrp = tid >> 3;
    const int jo   = (tid & 7) * 9;
    const int e0   = egrp * 4;

    // phase B: GEMM1 with packed f32x2 (edge pairs)
    unsigned long long a01[9], a23[9];
    #pragma unroll
    for (int jj = 0; jj < 9; jj++) {
        unsigned long long bv = pack2(svec[288 + jo + jj]);
        a01[jj] = bv; a23[jj] = bv;
    }
    #pragma unroll 4
    for (int k = 0; k < 72; k++) {
        ulonglong2 zp = *(const ulonglong2*)&szt[k*132 + e0];
        #pragma unroll
        for (int jj = 0; jj < 9; jj++) {
            unsigned long long wp = pack2(sW2[k*72 + jo + jj]);
            fma2(a01[jj], zp.x, wp);
            fma2(a23[jj], zp.y, wp);
        }
    }
    float acc[36];
    #pragma unroll
    for (int jj = 0; jj < 9; jj++) {
        unpack2(a01[jj], acc[jj],    acc[9+jj]);
        unpack2(a23[jj], acc[18+jj], acc[27+jj]);
    }

    // phase C: relu + partial mdot
    #pragma unroll
    for (int i = 0; i < 4; i++) {
        float pd = 0.f;
        #pragma unroll
        for (int jj = 0; jj < 9; jj++) {
            float v = fmaxf(acc[i*9 + jj], 0.f);
            acc[i*9 + jj] = v;
            pd = fmaf(v, svec[360 + jo + jj], pd);
        }
        atomicAdd(&smdot[e0 + i], pd);
    }
    __syncthreads();

    // phase D: sigmoid scale, m0 -> szt + global magg
    #pragma unroll
    for (int i = 0; i < 4; i++) {
        float sg = 1.f / (1.f + expf(-smdot[e0 + i]));
        #pragma unroll
        for (int jj = 0; jj < 9; jj++) acc[i*9 + jj] *= sg;
    }
    #pragma unroll
    for (int jj = 0; jj < 9; jj++) {
        float4 v4 = make_float4(acc[jj], acc[9+jj], acc[18+jj], acc[27+jj]);
        *(float4*)&szt[(jo + jj)*132 + e0] = v4;
    }
    #pragma unroll
    for (int i = 0; i < 4; i++) {
        float* ma = g_magg + (size_t)(b*NN + si[e0 + i])*72 + jo;
        #pragma unroll
        for (int jj = 0; jj < 9; jj++) atomicAdd(ma + jj, acc[i*9 + jj]);
    }
    __syncthreads();

    // phase E: coalesced m output
    {
        float* mo = out_m + (size_t)blk * (128*72);
        for (int t = tid; t < 128*72; t += 256) {
            int e = t / 72, c = t - e*72;
            mo[t] = szt[c*132 + e];
        }
    }

    // phase F: GEMM2 with packed f32x2 -> gate
    unsigned long long b01[9], b23[9];
    #pragma unroll
    for (int jj = 0; jj < 9; jj++) {
        unsigned long long bv = pack2(svec[432 + jo + jj]);
        b01[jj] = bv; b23[jj] = bv;
    }
    #pragma unroll 4
    for (int k = 0; k < 72; k++) {
        ulonglong2 zp = *(const ulonglong2*)&szt[k*132 + e0];
        #pragma unroll
        for (int jj = 0; jj < 9; jj++) {
            unsigned long long wp = pack2(sWx[k*72 + jo + jj]);
            fma2(b01[jj], zp.x, wp);
            fma2(b23[jj], zp.y, wp);
        }
    }
    float acc2[36];
    #pragma unroll
    for (int jj = 0; jj < 9; jj++) {
        unpack2(b01[jj], acc2[jj],    acc2[9+jj]);
        unpack2(b23[jj], acc2[18+jj], acc2[27+jj]);
    }
    #pragma unroll
    for (int i = 0; i < 4; i++) {
        float pg = 0.f;
        #pragma unroll
        for (int jj = 0; jj < 9; jj++)
            pg = fmaf(fmaxf(acc2[i*9 + jj], 0.f), svec[504 + jo + jj], pg);
        atomicAdd(&sgate[e0 + i], pg);
    }
    __syncthreads();

    // phase G: x-path atomics
    if (tid < 128) {
        int e = tid;
        int i = si[e], j = sj[e];
        float gate = sgate[e];
        const float* xi = x + (b*NN + i)*4;
        const float* xj = x + (b*NN + j)*4;
        float* ag = g_agg + (size_t)(b*NN + i)*4;
        #pragma unroll
        for (int d = 0; d < 4; d++) {
            float diff = xi[d] - xj[d];
            atomicAdd(ag + d, fminf(fmaxf(diff*gate, -100.f), 100.f));
        }
    }
}

// ---- node MLP pre-BN: block GEMM (128 nodes/block, K=148) ----
__global__ void __launch_bounds__(256) k_node_h1(
    const float* __restrict__ h, const float* __restrict__ na,
    const float* __restrict__ Wh1, const float* __restrict__ bh1)
{
    extern __shared__ float smh[];
    float* sW    = smh;
    float* sin_t = smh + 10656;
    int tid = threadIdx.x;
    int blk = blockIdx.x;

    for (int t = tid; t < 10656; t += 256) sW[t] = Wh1[t];
    for (int idx = tid; idx < 148*128; idx += 256) {
        int k = idx >> 7, n = idx & 127;
        int bn = blk*128 + n;
        float v;
        if (k < 72)       v = h[bn*72 + k];
        else if (k < 144) v = g_magg[bn*72 + (k-72)];
        else              v = na[bn*4 + (k-144)];
        sin_t[k*132 + n] = v;
    }
    __syncthreads();

    const int egrp = tid >> 3;
    const int jo   = (tid & 7) * 9;
    const int e0   = egrp * 4;

    float acc[36];
    #pragma unroll
    for (int jj = 0; jj < 9; jj++) {
        float bv = __ldg(bh1 + jo + jj);
        acc[jj] = bv; acc[9+jj] = bv; acc[18+jj] = bv; acc[27+jj] = bv;
    }
    #pragma unroll 4
    for (int k = 0; k < 148; k++) {
        float4 zv = *(const float4*)&sin_t[k*132 + e0];
        #pragma unroll
        for (int jj = 0; jj < 9; jj++) {
            float w = sW[k*72 + jo + jj];
            acc[jj]    = fmaf(zv.x, w, acc[jj]);
            acc[9+jj]  = fmaf(zv.y, w, acc[9+jj]);
            acc[18+jj] = fmaf(zv.z, w, acc[18+jj]);
            acc[27+jj] = fmaf(zv.w, w, acc[27+jj]);
        }
    }
    #pragma unroll
    for (int i = 0; i < 4; i++) {
        float* zr = g_z2 + (size_t)(blk*128 + e0 + i)*72 + jo;
        #pragma unroll
        for (int jj = 0; jj < 9; jj++) zr[jj] = acc[i*9 + jj];
    }
}

__global__ void k_fin_h(const float* __restrict__ gh, const float* __restrict__ bh) {
    int c = blockIdx.x;
    int tid = threadIdx.x;
    double s = 0.0, q = 0.0;
    for (int r = tid; r < BN; r += 128) {
        double v = (double)g_z2[r*72 + c];
        s += v; q += v*v;
    }
    __shared__ double rs[128], rq[128];
    rs[tid] = s; rq[tid] = q;
    __syncthreads();
    for (int off = 64; off > 0; off >>= 1) {
        if (tid < off) { rs[tid] += rs[tid+off]; rq[tid] += rq[tid+off]; }
        __syncthreads();
    }
    if (tid == 0) {
        double mu = rs[0] / (double)BN;
        double var = rq[0] / (double)BN - mu*mu;
        float a = gh[c] * (float)(1.0 / sqrt(var + 1e-5));
        g_bn_h[c] = a;
        g_bn_h[72 + c] = bh[c] - (float)mu * a;
    }
}

// ---- node output: block GEMM (128 nodes/block, K=72) + x_out ----
__global__ void __launch_bounds__(256) k_node_h2(
    const float* __restrict__ h, const float* __restrict__ x,
    const float* __restrict__ Wh2, const float* __restrict__ bh2,
    float* __restrict__ out)
{
    extern __shared__ float smh[];
    float* sW   = smh;
    float* sv_t = smh + 5184;
    float* sbn  = smh + 14688;
    int tid = threadIdx.x;
    int blk = blockIdx.x;

    for (int t = tid; t < 5184; t += 256) sW[t] = Wh2[t];
    if (tid < 144) sbn[tid] = g_bn_h[tid];
    __syncthreads();
    for (int idx = tid; idx < 72*128; idx += 256) {
        int c = idx >> 7, n = idx & 127;
        float v = g_z2[(size_t)(blk*128 + n)*72 + c];
        sv_t[c*132 + n] = fmaxf(fmaf(v, sbn[c], sbn[72 + c]), 0.f);
    }
    __syncthreads();

    const int egrp = tid >> 3;
    const int jo   = (tid & 7) * 9;
    const int e0   = egrp * 4;

    float acc[36];
    #pragma unroll
    for (int jj = 0; jj < 9; jj++) {
        float bv = __ldg(bh2 + jo + jj);
        acc[jj] = bv; acc[9+jj] = bv; acc[18+jj] = bv; acc[27+jj] = bv;
    }
    #pragma unroll 4
    for (int k = 0; k < 72; k++) {
        float4 zv = *(const float4*)&sv_t[k*132 + e0];
        #pragma unroll
        for (int jj = 0; jj < 9; jj++) {
            float w = sW[k*72 + jo + jj];
            acc[jj]    = fmaf(zv.x, w, acc[jj]);
            acc[9+jj]  = fmaf(zv.y, w, acc[9+jj]);
            acc[18+jj] = fmaf(zv.z, w, acc[18+jj]);
            acc[27+jj] = fmaf(zv.w, w, acc[27+jj]);
        }
    }
    #pragma unroll
    for (int i = 0; i < 4; i++) {
        int bn = blk*128 + e0 + i;
        const float* hr = h + (size_t)bn*72 + jo;
        float* oh = out + (size_t)bn*72 + jo;
        #pragma unroll
        for (int jj = 0; jj < 9; jj++) oh[jj] = hr[jj] + acc[i*9 + jj];
    }

    if (tid < 128) {
        int bn = blk*128 + tid;
        float cn = fmaxf((float)g_cnt[bn], 1.f);
        float inv = 1.f / cn;
        float* ox = out + BN*HH + (size_t)bn*4;
        #pragma unroll
        for (int d = 0; d < 4; d++)
            ox[d] = x[bn*4 + d] + g_agg[bn*4 + d] * inv;
    }
}

extern "C" void kernel_launch(void* const* d_in, const int* in_sizes, int n_in,
                              void* d_out, int out_size)
{
    (void)in_sizes; (void)n_in; (void)out_size;
    const float* h   = (const float*)d_in[0];
    const float* x   = (const float*)d_in[1];
    const int*   ei  = (const int*)  d_in[2];
    const int*   ej  = (const int*)  d_in[3];
    const float* na  = (const float*)d_in[4];
    const float* We1 = (const float*)d_in[5];
    const float* g1  = (const float*)d_in[6];
    const float* b1  = (const float*)d_in[7];
    const float* We2 = (const float*)d_in[8];
    const float* be2 = (const float*)d_in[9];
    const float* Wm  = (const float*)d_in[10];
    const float* bm  = (const float*)d_in[11];
    const float* Wx1 = (const float*)d_in[12];
    const float* bx1 = (const float*)d_in[13];
    const float* Wx2 = (const float*)d_in[14];
    const float* Wh1 = (const float*)d_in[15];
    const float* bh1 = (const float*)d_in[16];
    const float* gh  = (const float*)d_in[17];
    const float* bhv = (const float*)d_in[18];
    const float* Wh2 = (const float*)d_in[19];
    const float* bh2 = (const float*)d_in[20];

    float* out = (float*)d_out;
    float* out_m = out + BN*HH + BN*4;

    cudaFuncSetAttribute(k_m, cudaFuncAttributeMaxDynamicSharedMemorySize,
                         SM_TOT * (int)sizeof(float));
    cudaFuncSetAttribute(k_node_h1, cudaFuncAttributeMaxDynamicSharedMemorySize,
                         30192 * (int)sizeof(float));
    cudaFuncSetAttribute(k_node_h2, cudaFuncAttributeMaxDynamicSharedMemorySize,
                         14832 * (int)sizeof(float));

    k_pre<<<BB, 128>>>(h, We1);                         // launch 1 (includes zeroing)
    k_stats<<<256, 288>>>(x, ei, ej, We1);              // launch 2
    k_fin_e<<<1, 72>>>(g1, b1);                         // launch 3
    k_m<<<ETOT/128, 256, SM_TOT*(int)sizeof(float)>>>(  // launch 4  <-- profile slot
        x, ei, ej, We1, We2, be2, Wm, bm, Wx1, bx1, Wx2, out_m);
    k_node_h1<<<BB, 256, 30192*(int)sizeof(float)>>>(h, na, Wh1, bh1);
    k_fin_h<<<72, 128>>>(gh, bhv);
    k_node_h2<<<BB, 256, 14832*(int)sizeof(float)>>>(h, x, Wh2, bh2, out);
}

// round 14
// speedup vs baseline: 1.0446x; 1.0422x over previous
#include <cuda_runtime.h>
#include <math.h>

#define BB 32
#define NN 128
#define EE 16384
#define ETOT (BB*EE)
#define DD 72
#define HH 72
#define BN (BB*NN)

// ---------------- device scratch ----------------
__device__ float  g_P[BN*HH];
__device__ float  g_Q[BN*HH];
__device__ double g_esum[HH];
__device__ double g_esq[HH];
__device__ float  g_bn_e[2*HH];
__device__ float  g_magg[BN*HH];
__device__ float  g_agg[BN*4];
__device__ int    g_cnt[BN];
__device__ float  g_z2[BN*HH];
__device__ float  g_bn_h[2*HH];

__device__ __forceinline__ float psi_f(float p) {
    return copysignf(log1pf(fabsf(p)), p);
}

// packed fp32 helpers (FFMA2 path — PTX-only)
__device__ __forceinline__ unsigned long long pack2(float v) {
    unsigned long long r;
    asm("mov.b64 %0, {%1, %1};" : "=l"(r) : "f"(v));
    return r;
}
__device__ __forceinline__ void fma2(unsigned long long& d,
                                     unsigned long long a, unsigned long long b) {
    asm("fma.rn.f32x2 %0, %1, %2, %0;" : "+l"(d) : "l"(a), "l"(b));
}
__device__ __forceinline__ void unpack2(unsigned long long v, float& lo, float& hi) {
    asm("mov.b64 {%0, %1}, %2;" : "=f"(lo), "=f"(hi) : "l"(v));
}

// ---- per-node P,Q = h @ We1[:144]; also zero-init accumulators ----
__global__ void __launch_bounds__(128) k_pre(
    const float* __restrict__ h, const float* __restrict__ We1)
{
    __shared__ float sW[144*72];
    int tid = threadIdx.x;
    int gid = blockIdx.x * 128 + tid;      // 0..4095

    for (int t = gid; t < BN*HH; t += BN) g_magg[t] = 0.f;
    for (int t = gid; t < BN*4;  t += BN) g_agg[t]  = 0.f;
    g_cnt[gid] = 0;
    if (gid < HH) { g_esum[gid] = 0.0; g_esq[gid] = 0.0; }

    for (int t = tid; t < 144*72; t += 128) sW[t] = We1[t];
    __syncthreads();

    int bn = gid;
    float hv[72];
    for (int k = 0; k < 72; k++) hv[k] = h[bn*72 + k];
    float* Pr = g_P + bn*72;
    float* Qr = g_Q + bn*72;
    for (int jc = 0; jc < 72; jc++) {
        float a = 0.f, b2 = 0.f;
        for (int k = 0; k < 72; k++) {
            a  += hv[k] * sW[k*72 + jc];
            b2 += hv[k] * sW[(72+k)*72 + jc];
        }
        Pr[jc] = a;
        Qr[jc] = b2;
    }
}

// ---- BN stats, channel-parallel: 4 edge-groups x 72 channels ----
__global__ void __launch_bounds__(288) k_stats(
    const float* __restrict__ x,
    const int* __restrict__ ei, const int* __restrict__ ej,
    const float* __restrict__ We1)
{
    __shared__ float snv[256], sdv[256];
    __shared__ int   si[256], sj[256];
    __shared__ float ssum[72], ssq[72];
    int tid = threadIdx.x;
    int g = tid / 72;
    int c = tid - g*72;
    if (tid < 72) { ssum[tid] = 0.f; ssq[tid] = 0.f; }
    float w1 = We1[144*72 + c];
    float w2 = We1[145*72 + c];

    int b = blockIdx.x >> 3;
    float s = 0.f, q = 0.f;

    #pragma unroll 1
    for (int t = 0; t < 8; t++) {
        __syncthreads();
        if (tid < 256) {
            int eg = blockIdx.x*2048 + t*256 + tid;
            int i = ei[eg], j = ej[eg];
            atomicAdd(&g_cnt[b*NN + i], 1);
            si[tid] = i; sj[tid] = j;
            const float* xi = x + (b*NN + i)*4;
            const float* xj = x + (b*NN + j)*4;
            float d0 = xi[0]-xj[0], d1 = xi[1]-xj[1], d2 = xi[2]-xj[2], d3 = xi[3]-xj[3];
            snv[tid] = psi_f(d0*d0 - d1*d1 - d2*d2 - d3*d3);
            sdv[tid] = psi_f(xi[0]*xj[0] - xi[1]*xj[1] - xi[2]*xj[2] - xi[3]*xj[3]);
        }
        __syncthreads();
        int e0 = g * 64;
        #pragma unroll 4
        for (int e = e0; e < e0 + 64; e++) {
            float v = g_P[(size_t)(b*NN + si[e])*72 + c]
                    + g_Q[(size_t)(b*NN + sj[e])*72 + c]
                    + snv[e]*w1 + sdv[e]*w2;
            s += v; q += v*v;
        }
    }
    atomicAdd(&ssum[c], s);
    atomicAdd(&ssq[c], q);
    __syncthreads();
    if (tid < 72) {
        atomicAdd(&g_esum[tid], (double)ssum[tid]);
        atomicAdd(&g_esq[tid],  (double)ssq[tid]);
    }
}

__global__ void k_fin_e(const float* __restrict__ g1, const float* __restrict__ b1) {
    int c = threadIdx.x;
    if (c < 72) {
        double inv = 1.0 / (double)ETOT;
        double mu  = g_esum[c] * inv;
        double var = g_esq[c] * inv - mu*mu;
        float a = g1[c] * (float)(1.0 / sqrt(var + 1e-5));
        g_bn_e[c] = a;
        g_bn_e[72 + c] = b1[c] - (float)mu * a;
    }
}

// ---- main edge kernel: 128 edges/block; transposed weights, 3 blocks/SM ----
// dynamic smem layout (floats):
//   sWt   [72*76 = 5472] @ 0      (transposed weights: [j][k], stride 76; re-staged)
//   szt   [72*132= 9504] @ 5472   (zb then m0, transposed [c][e], stride 132)
//   svec  [576]          @ 14976
//   smdot [128]          @ 15552
//   sgate [128]          @ 15680
//   si,sj [128 each]     @ 15808, 15936
#define SM_WT   0
#define SM_ZT   5472
#define SM_VEC  14976
#define SM_MDOT 15552
#define SM_GATE 15680
#define SM_SI   15808
#define SM_SJ   15936
#define SM_TOT  16064   /* floats -> 64256 bytes -> 3 blocks/SM */

__global__ void __launch_bounds__(256, 3) k_m(
    const float* __restrict__ x,
    const int* __restrict__ ei, const int* __restrict__ ej,
    const float* __restrict__ We1, const float* __restrict__ We2,
    const float* __restrict__ be2, const float* __restrict__ Wm,
    const float* __restrict__ bm, const float* __restrict__ Wx1,
    const float* __restrict__ bx1, const float* __restrict__ Wx2,
    float* __restrict__ out_m)
{
    extern __shared__ float sm[];
    float* sWt   = sm + SM_WT;
    float* szt   = sm + SM_ZT;
    float* svec  = sm + SM_VEC;
    float* smdot = sm + SM_MDOT;
    float* sgate = sm + SM_GATE;
    int*   si    = (int*)(sm + SM_SI);
    int*   sj    = (int*)(sm + SM_SJ);

    const int tid = threadIdx.x;
    const int blk = blockIdx.x;
    const int b   = blk >> 7;

    // stage We2 transposed: sWt[j*76 + k] = We2[k*72 + j]
    for (int t = tid; t < 5184; t += 256) {
        int k = t / 72, j = t - k*72;
        sWt[j*76 + k] = We2[t];
    }
    if (tid < 72) {
        svec[tid]        = g_bn_e[tid];
        svec[72  + tid]  = g_bn_e[72 + tid];
        svec[144 + tid]  = We1[144*72 + tid];
        svec[216 + tid]  = We1[145*72 + tid];
        svec[288 + tid]  = be2[tid];
        svec[360 + tid]  = Wm[tid];
        svec[432 + tid]  = bx1[tid];
        svec[504 + tid]  = Wx2[tid];
    }
    if (tid < 128) {
        int eg = blk*128 + tid;
        si[tid] = ei[eg];
        sj[tid] = ej[eg];
        smdot[tid] = bm[0];
        sgate[tid] = 0.f;
    }
    __syncthreads();

    // phase A: zb = relu(BN(z1)) into szt (transposed), float4 gathers
    {
        int e = tid >> 1, half = tid & 1, c0 = half*36;
        int i = si[e], j = sj[e];
        const float* xi = x + (b*NN + i)*4;
        const float* xj = x + (b*NN + j)*4;
        float d0 = xi[0]-xj[0], d1 = xi[1]-xj[1], d2 = xi[2]-xj[2], d3 = xi[3]-xj[3];
        float nv = psi_f(d0*d0 - d1*d1 - d2*d2 - d3*d3);
        float dv = psi_f(xi[0]*xj[0] - xi[1]*xj[1] - xi[2]*xj[2] - xi[3]*xj[3]);
        const float4* Pr = (const float4*)(g_P + (size_t)(b*NN + i)*72 + c0);
        const float4* Qr = (const float4*)(g_Q + (size_t)(b*NN + j)*72 + c0);
        #pragma unroll
        for (int c4 = 0; c4 < 9; c4++) {
            float4 p = Pr[c4];
            float4 q = Qr[c4];
            int cc = c0 + c4*4;
            float v0 = p.x + q.x + nv*svec[144+cc+0] + dv*svec[216+cc+0];
            float v1 = p.y + q.y + nv*svec[144+cc+1] + dv*svec[216+cc+1];
            float v2 = p.z + q.z + nv*svec[144+cc+2] + dv*svec[216+cc+2];
            float v3 = p.w + q.w + nv*svec[144+cc+3] + dv*svec[216+cc+3];
            szt[(cc+0)*132 + e] = fmaxf(fmaf(v0, svec[cc+0], svec[72+cc+0]), 0.f);
            szt[(cc+1)*132 + e] = fmaxf(fmaf(v1, svec[cc+1], svec[72+cc+1]), 0.f);
            szt[(cc+2)*132 + e] = fmaxf(fmaf(v2, svec[cc+2], svec[72+cc+2]), 0.f);
            szt[(cc+3)*132 + e] = fmaxf(fmaf(v3, svec[cc+3], svec[72+cc+3]), 0.f);
        }
    }
    __syncthreads();

    const int egrp = tid >> 3;
    const int jo   = (tid & 7) * 9;
    const int e0   = egrp * 4;

    // phase B: GEMM1 — k-unrolled x4, float4 weight loads from transposed sWt
    unsigned long long a01[9], a23[9];
    #pragma unroll
    for (int jj = 0; jj < 9; jj++) {
        unsigned long long bv = pack2(svec[288 + jo + jj]);
        a01[jj] = bv; a23[jj] = bv;
    }
    #pragma unroll 2
    for (int k4 = 0; k4 < 72; k4 += 4) {
        ulonglong2 zp0 = *(const ulonglong2*)&szt[(k4+0)*132 + e0];
        ulonglong2 zp1 = *(const ulonglong2*)&szt[(k4+1)*132 + e0];
        ulonglong2 zp2 = *(const ulonglong2*)&szt[(k4+2)*132 + e0];
        ulonglong2 zp3 = *(const ulonglong2*)&szt[(k4+3)*132 + e0];
        #pragma unroll
        for (int jj = 0; jj < 9; jj++) {
            float4 w = *(const float4*)&sWt[(jo + jj)*76 + k4];
            unsigned long long w0 = pack2(w.x), w1 = pack2(w.y);
            unsigned long long w2 = pack2(w.z), w3 = pack2(w.w);
            fma2(a01[jj], zp0.x, w0); fma2(a23[jj], zp0.y, w0);
            fma2(a01[jj], zp1.x, w1); fma2(a23[jj], zp1.y, w1);
            fma2(a01[jj], zp2.x, w2); fma2(a23[jj], zp2.y, w2);
            fma2(a01[jj], zp3.x, w3); fma2(a23[jj], zp3.y, w3);
        }
    }
    float acc[36];
    #pragma unroll
    for (int jj = 0; jj < 9; jj++) {
        unpack2(a01[jj], acc[jj],    acc[9+jj]);
        unpack2(a23[jj], acc[18+jj], acc[27+jj]);
    }

    // phase C: relu + partial mdot
    #pragma unroll
    for (int i = 0; i < 4; i++) {
        float pd = 0.f;
        #pragma unroll
        for (int jj = 0; jj < 9; jj++) {
            float v = fmaxf(acc[i*9 + jj], 0.f);
            acc[i*9 + jj] = v;
            pd = fmaf(v, svec[360 + jo + jj], pd);
        }
        atomicAdd(&smdot[e0 + i], pd);
    }
    __syncthreads();   // GEMM1 reads of sWt/szt done; smdot final

    // phase D: sigmoid scale; m0 -> szt; global magg; restage sWt = Wx1^T
    #pragma unroll
    for (int i = 0; i < 4; i++) {
        float sg = 1.f / (1.f + expf(-smdot[e0 + i]));
        #pragma unroll
        for (int jj = 0; jj < 9; jj++) acc[i*9 + jj] *= sg;
    }
    #pragma unroll
    for (int jj = 0; jj < 9; jj++) {
        float4 v4 = make_float4(acc[jj], acc[9+jj], acc[18+jj], acc[27+jj]);
        *(float4*)&szt[(jo + jj)*132 + e0] = v4;
    }
    #pragma unroll
    for (int i = 0; i < 4; i++) {
        float* ma = g_magg + (size_t)(b*NN + si[e0 + i])*72 + jo;
        #pragma unroll
        for (int jj = 0; jj < 9; jj++) atomicAdd(ma + jj, acc[i*9 + jj]);
    }
    for (int t = tid; t < 5184; t += 256) {
        int k = t / 72, j = t - k*72;
        sWt[j*76 + k] = Wx1[t];
    }
    __syncthreads();   // m0 + restaged weights ready

    // phase E: coalesced m output
    {
        float* mo = out_m + (size_t)blk * (128*72);
        for (int t = tid; t < 128*72; t += 256) {
            int e = t / 72, c = t - e*72;
            mo[t] = szt[c*132 + e];
        }
    }

    // phase F: GEMM2 -> gate
    unsigned long long b01[9], b23[9];
    #pragma unroll
    for (int jj = 0; jj < 9; jj++) {
        unsigned long long bv = pack2(svec[432 + jo + jj]);
        b01[jj] = bv; b23[jj] = bv;
    }
    #pragma unroll 2
    for (int k4 = 0; k4 < 72; k4 += 4) {
        ulonglong2 zp0 = *(const ulonglong2*)&szt[(k4+0)*132 + e0];
        ulonglong2 zp1 = *(const ulonglong2*)&szt[(k4+1)*132 + e0];
        ulonglong2 zp2 = *(const ulonglong2*)&szt[(k4+2)*132 + e0];
        ulonglong2 zp3 = *(const ulonglong2*)&szt[(k4+3)*132 + e0];
        #pragma unroll
        for (int jj = 0; jj < 9; jj++) {
            float4 w = *(const float4*)&sWt[(jo + jj)*76 + k4];
            unsigned long long w0 = pack2(w.x), w1 = pack2(w.y);
            unsigned long long w2 = pack2(w.z), w3 = pack2(w.w);
            fma2(b01[jj], zp0.x, w0); fma2(b23[jj], zp0.y, w0);
            fma2(b01[jj], zp1.x, w1); fma2(b23[jj], zp1.y, w1);
            fma2(b01[jj], zp2.x, w2); fma2(b23[jj], zp2.y, w2);
            fma2(b01[jj], zp3.x, w3); fma2(b23[jj], zp3.y, w3);
        }
    }
    float acc2[36];
    #pragma unroll
    for (int jj = 0; jj < 9; jj++) {
        unpack2(b01[jj], acc2[jj],    acc2[9+jj]);
        unpack2(b23[jj], acc2[18+jj], acc2[27+jj]);
    }
    #pragma unroll
    for (int i = 0; i < 4; i++) {
        float pg = 0.f;
        #pragma unroll
        for (int jj = 0; jj < 9; jj++)
            pg = fmaf(fmaxf(acc2[i*9 + jj], 0.f), svec[504 + jo + jj], pg);
        atomicAdd(&sgate[e0 + i], pg);
    }
    __syncthreads();

    // phase G: x-path atomics
    if (tid < 128) {
        int e = tid;
        int i = si[e], j = sj[e];
        float gate = sgate[e];
        const float* xi = x + (b*NN + i)*4;
        const float* xj = x + (b*NN + j)*4;
        float* ag = g_agg + (size_t)(b*NN + i)*4;
        #pragma unroll
        for (int d = 0; d < 4; d++) {
            float diff = xi[d] - xj[d];
            atomicAdd(ag + d, fminf(fmaxf(diff*gate, -100.f), 100.f));
        }
    }
}

// ---- node MLP pre-BN: block GEMM (128 nodes/block, K=148) ----
__global__ void __launch_bounds__(256) k_node_h1(
    const float* __restrict__ h, const float* __restrict__ na,
    const float* __restrict__ Wh1, const float* __restrict__ bh1)
{
    extern __shared__ float smh[];
    float* sW    = smh;
    float* sin_t = smh + 10656;
    int tid = threadIdx.x;
    int blk = blockIdx.x;

    for (int t = tid; t < 10656; t += 256) sW[t] = Wh1[t];
    for (int idx = tid; idx < 148*128; idx += 256) {
        int k = idx >> 7, n = idx & 127;
        int bn = blk*128 + n;
        float v;
        if (k < 72)       v = h[bn*72 + k];
        else if (k < 144) v = g_magg[bn*72 + (k-72)];
        else              v = na[bn*4 + (k-144)];
        sin_t[k*132 + n] = v;
    }
    __syncthreads();

    const int egrp = tid >> 3;
    const int jo   = (tid & 7) * 9;
    const int e0   = egrp * 4;

    float acc[36];
    #pragma unroll
    for (int jj = 0; jj < 9; jj++) {
        float bv = __ldg(bh1 + jo + jj);
        acc[jj] = bv; acc[9+jj] = bv; acc[18+jj] = bv; acc[27+jj] = bv;
    }
    #pragma unroll 4
    for (int k = 0; k < 148; k++) {
        float4 zv = *(const float4*)&sin_t[k*132 + e0];
        #pragma unroll
        for (int jj = 0; jj < 9; jj++) {
            float w = sW[k*72 + jo + jj];
            acc[jj]    = fmaf(zv.x, w, acc[jj]);
            acc[9+jj]  = fmaf(zv.y, w, acc[9+jj]);
            acc[18+jj] = fmaf(zv.z, w, acc[18+jj]);
            acc[27+jj] = fmaf(zv.w, w, acc[27+jj]);
        }
    }
    #pragma unroll
    for (int i = 0; i < 4; i++) {
        float* zr = g_z2 + (size_t)(blk*128 + e0 + i)*72 + jo;
        #pragma unroll
        for (int jj = 0; jj < 9; jj++) zr[jj] = acc[i*9 + jj];
    }
}

__global__ void k_fin_h(const float* __restrict__ gh, const float* __restrict__ bh) {
    int c = blockIdx.x;
    int tid = threadIdx.x;
    double s = 0.0, q = 0.0;
    for (int r = tid; r < BN; r += 128) {
        double v = (double)g_z2[r*72 + c];
        s += v; q += v*v;
    }
    __shared__ double rs[128], rq[128];
    rs[tid] = s; rq[tid] = q;
    __syncthreads();
    for (int off = 64; off > 0; off >>= 1) {
        if (tid < off) { rs[tid] += rs[tid+off]; rq[tid] += rq[tid+off]; }
        __syncthreads();
    }
    if (tid == 0) {
        double mu = rs[0] / (double)BN;
        double var = rq[0] / (double)BN - mu*mu;
        float a = gh[c] * (float)(1.0 / sqrt(var + 1e-5));
        g_bn_h[c] = a;
        g_bn_h[72 + c] = bh[c] - (float)mu * a;
    }
}

// ---- node output: block GEMM (128 nodes/block, K=72) + x_out ----
__global__ void __launch_bounds__(256) k_node_h2(
    const float* __restrict__ h, const float* __restrict__ x,
    const float* __restrict__ Wh2, const float* __restrict__ bh2,
    float* __restrict__ out)
{
    extern __shared__ float smh[];
    float* sW   = smh;
    float* sv_t = smh + 5184;
    float* sbn  = smh + 14688;
    int tid = threadIdx.x;
    int blk = blockIdx.x;

    for (int t = tid; t < 5184; t += 256) sW[t] = Wh2[t];
    if (tid < 144) sbn[tid] = g_bn_h[tid];
    __syncthreads();
    for (int idx = tid; idx < 72*128; idx += 256) {
        int c = idx >> 7, n = idx & 127;
        float v = g_z2[(size_t)(blk*128 + n)*72 + c];
        sv_t[c*132 + n] = fmaxf(fmaf(v, sbn[c], sbn[72 + c]), 0.f);
    }
    __syncthreads();

    const int egrp = tid >> 3;
    const int jo   = (tid & 7) * 9;
    const int e0   = egrp * 4;

    float acc[36];
    #pragma unroll
    for (int jj = 0; jj < 9; jj++) {
        float bv = __ldg(bh2 + jo + jj);
        acc[jj] = bv; acc[9+jj] = bv; acc[18+jj] = bv; acc[27+jj] = bv;
    }
    #pragma unroll 4
    for (int k = 0; k < 72; k++) {
        float4 zv = *(const float4*)&sv_t[k*132 + e0];
        #pragma unroll
        for (int jj = 0; jj < 9; jj++) {
            float w = sW[k*72 + jo + jj];
            acc[jj]    = fmaf(zv.x, w, acc[jj]);
            acc[9+jj]  = fmaf(zv.y, w, acc[9+jj]);
            acc[18+jj] = fmaf(zv.z, w, acc[18+jj]);
            acc[27+jj] = fmaf(zv.w, w, acc[27+jj]);
        }
    }
    #pragma unroll
    for (int i = 0; i < 4; i++) {
        int bn = blk*128 + e0 + i;
        const float* hr = h + (size_t)bn*72 + jo;
        float* oh = out + (size_t)bn*72 + jo;
        #pragma unroll
        for (int jj = 0; jj < 9; jj++) oh[jj] = hr[jj] + acc[i*9 + jj];
    }

    if (tid < 128) {
        int bn = blk*128 + tid;
        float cn = fmaxf((float)g_cnt[bn], 1.f);
        float inv = 1.f / cn;
        float* ox = out + BN*HH + (size_t)bn*4;
        #pragma unroll
        for (int d = 0; d < 4; d++)
            ox[d] = x[bn*4 + d] + g_agg[bn*4 + d] * inv;
    }
}

extern "C" void kernel_launch(void* const* d_in, const int* in_sizes, int n_in,
                              void* d_out, int out_size)
{
    (void)in_sizes; (void)n_in; (void)out_size;
    const float* h   = (const float*)d_in[0];
    const float* x   = (const float*)d_in[1];
    const int*   ei  = (const int*)  d_in[2];
    const int*   ej  = (const int*)  d_in[3];
    const float* na  = (const float*)d_in[4];
    const float* We1 = (const float*)d_in[5];
    const float* g1  = (const float*)d_in[6];
    const float* b1  = (const float*)d_in[7];
    const float* We2 = (const float*)d_in[8];
    const float* be2 = (const float*)d_in[9];
    const float* Wm  = (const float*)d_in[10];
    const float* bm  = (const float*)d_in[11];
    const float* Wx1 = (const float*)d_in[12];
    const float* bx1 = (const float*)d_in[13];
    const float* Wx2 = (const float*)d_in[14];
    const float* Wh1 = (const float*)d_in[15];
    const float* bh1 = (const float*)d_in[16];
    const float* gh  = (const float*)d_in[17];
    const float* bhv = (const float*)d_in[18];
    const float* Wh2 = (const float*)d_in[19];
    const float* bh2 = (const float*)d_in[20];

    float* out = (float*)d_out;
    float* out_m = out + BN*HH + BN*4;

    cudaFuncSetAttribute(k_m, cudaFuncAttributeMaxDynamicSharedMemorySize,
                         SM_TOT * (int)sizeof(float));
    cudaFuncSetAttribute(k_node_h1, cudaFuncAttributeMaxDynamicSharedMemorySize,
                         30192 * (int)sizeof(float));
    cudaFuncSetAttribute(k_node_h2, cudaFuncAttributeMaxDynamicSharedMemorySize,
                         14832 * (int)sizeof(float));

    k_pre<<<BB, 128>>>(h, We1);                         // launch 1 (includes zeroing)
    k_stats<<<256, 288>>>(x, ei, ej, We1);              // launch 2
    k_fin_e<<<1, 72>>>(g1, b1);                         // launch 3
    k_m<<<ETOT/128, 256, SM_TOT*(int)sizeof(float)>>>(  // launch 4  <-- profile slot
        x, ei, ej, We1, We2, be2, Wm, bm, Wx1, bx1, Wx2, out_m);
    k_node_h1<<<BB, 256, 30192*(int)sizeof(float)>>>(h, na, Wh1, bh1);
    k_fin_h<<<72, 128>>>(gh, bhv);
    k_node_h2<<<BB, 256, 14832*(int)sizeof(float)>>>(h, x, Wh2, bh2, out);
}

// round 15
// speedup vs baseline: 1.4457x; 1.3839x over previous
#include <cuda_runtime.h>
#include <math.h>

#define BB 32
#define NN 128
#define EE 16384
#define ETOT (BB*EE)
#define DD 72
#define HH 72
#define BN (BB*NN)

// ---------------- device scratch ----------------
__device__ float  g_P[BN*HH];
__device__ float  g_Q[BN*HH];
__device__ double g_esum[HH];
__device__ double g_esq[HH];
__device__ float  g_bn_e[2*HH];
__device__ __align__(16) float g_magg[BN*HH];
__device__ __align__(16) float g_agg[BN*4];
__device__ int    g_cnt[BN];
__device__ float  g_z2[BN*HH];
__device__ float  g_bn_h[2*HH];

__device__ __forceinline__ float psi_f(float p) {
    return copysignf(log1pf(fabsf(p)), p);
}

// packed fp32 helpers (FFMA2 path — PTX-only)
__device__ __forceinline__ unsigned long long pack2(float v) {
    unsigned long long r;
    asm("mov.b64 %0, {%1, %1};" : "=l"(r) : "f"(v));
    return r;
}
__device__ __forceinline__ void fma2(unsigned long long& d,
                                     unsigned long long a, unsigned long long b) {
    asm("fma.rn.f32x2 %0, %1, %2, %0;" : "+l"(d) : "l"(a), "l"(b));
}
__device__ __forceinline__ void unpack2(unsigned long long v, float& lo, float& hi) {
    asm("mov.b64 {%0, %1}, %2;" : "=f"(lo), "=f"(hi) : "l"(v));
}
__device__ __forceinline__ void red_v4(float* p, float a, float b, float c, float d) {
    asm volatile("red.global.add.v4.f32 [%0], {%1, %2, %3, %4};"
                 :: "l"(p), "f"(a), "f"(b), "f"(c), "f"(d) : "memory");
}

// ---- per-node P,Q = h @ We1[:144]; also zero-init accumulators ----
__global__ void __launch_bounds__(128) k_pre(
    const float* __restrict__ h, const float* __restrict__ We1)
{
    __shared__ float sW[144*72];
    int tid = threadIdx.x;
    int gid = blockIdx.x * 128 + tid;      // 0..4095

    for (int t = gid; t < BN*HH; t += BN) g_magg[t] = 0.f;
    for (int t = gid; t < BN*4;  t += BN) g_agg[t]  = 0.f;
    g_cnt[gid] = 0;
    if (gid < HH) { g_esum[gid] = 0.0; g_esq[gid] = 0.0; }

    for (int t = tid; t < 144*72; t += 128) sW[t] = We1[t];
    __syncthreads();

    int bn = gid;
    float hv[72];
    for (int k = 0; k < 72; k++) hv[k] = h[bn*72 + k];
    float* Pr = g_P + bn*72;
    float* Qr = g_Q + bn*72;
    for (int jc = 0; jc < 72; jc++) {
        float a = 0.f, b2 = 0.f;
        for (int k = 0; k < 72; k++) {
            a  += hv[k] * sW[k*72 + jc];
            b2 += hv[k] * sW[(72+k)*72 + jc];
        }
        Pr[jc] = a;
        Qr[jc] = b2;
    }
}

// ---- BN stats, channel-parallel: 4 edge-groups x 72 channels ----
__global__ void __launch_bounds__(288) k_stats(
    const float* __restrict__ x,
    const int* __restrict__ ei, const int* __restrict__ ej,
    const float* __restrict__ We1)
{
    __shared__ float snv[256], sdv[256];
    __shared__ int   si[256], sj[256];
    __shared__ float ssum[72], ssq[72];
    int tid = threadIdx.x;
    int g = tid / 72;
    int c = tid - g*72;
    if (tid < 72) { ssum[tid] = 0.f; ssq[tid] = 0.f; }
    float w1 = We1[144*72 + c];
    float w2 = We1[145*72 + c];

    int b = blockIdx.x >> 3;
    float s = 0.f, q = 0.f;

    #pragma unroll 1
    for (int t = 0; t < 8; t++) {
        __syncthreads();
        if (tid < 256) {
            int eg = blockIdx.x*2048 + t*256 + tid;
            int i = ei[eg], j = ej[eg];
            atomicAdd(&g_cnt[b*NN + i], 1);
            si[tid] = i; sj[tid] = j;
            const float* xi = x + (b*NN + i)*4;
            const float* xj = x + (b*NN + j)*4;
            float d0 = xi[0]-xj[0], d1 = xi[1]-xj[1], d2 = xi[2]-xj[2], d3 = xi[3]-xj[3];
            snv[tid] = psi_f(d0*d0 - d1*d1 - d2*d2 - d3*d3);
            sdv[tid] = psi_f(xi[0]*xj[0] - xi[1]*xj[1] - xi[2]*xj[2] - xi[3]*xj[3]);
        }
        __syncthreads();
        int e0 = g * 64;
        #pragma unroll 4
        for (int e = e0; e < e0 + 64; e++) {
            float v = g_P[(size_t)(b*NN + si[e])*72 + c]
                    + g_Q[(size_t)(b*NN + sj[e])*72 + c]
                    + snv[e]*w1 + sdv[e]*w2;
            s += v; q += v*v;
        }
    }
    atomicAdd(&ssum[c], s);
    atomicAdd(&ssq[c], q);
    __syncthreads();
    if (tid < 72) {
        atomicAdd(&g_esum[tid], (double)ssum[tid]);
        atomicAdd(&g_esq[tid],  (double)ssq[tid]);
    }
}

__global__ void k_fin_e(const float* __restrict__ g1, const float* __restrict__ b1) {
    int c = threadIdx.x;
    if (c < 72) {
        double inv = 1.0 / (double)ETOT;
        double mu  = g_esum[c] * inv;
        double var = g_esq[c] * inv - mu*mu;
        float a = g1[c] * (float)(1.0 / sqrt(var + 1e-5));
        g_bn_e[c] = a;
        g_bn_e[72 + c] = b1[c] - (float)mu * a;
    }
}

// ---- main edge kernel: 128 edges/block; shuffle reductions; red.v4 ----
// dynamic smem layout (floats):
//   sWt   [72*76 = 5472] @ 0      (transposed weights [j][k], stride 76; re-staged)
//   szt   [72*132= 9504] @ 5472   (zb then m0, transposed [c][e], stride 132)
//   svec  [576]          @ 14976
//   si,sj [128 each]     @ 15552, 15680
#define SM_WT   0
#define SM_ZT   5472
#define SM_VEC  14976
#define SM_SI   15552
#define SM_SJ   15680
#define SM_TOT  15808   /* floats -> 63232 bytes -> 3 blocks/SM */

__global__ void __launch_bounds__(256, 3) k_m(
    const float* __restrict__ x,
    const int* __restrict__ ei, const int* __restrict__ ej,
    const float* __restrict__ We1, const float* __restrict__ We2,
    const float* __restrict__ be2, const float* __restrict__ Wm,
    const float* __restrict__ bm, const float* __restrict__ Wx1,
    const float* __restrict__ bx1, const float* __restrict__ Wx2,
    float* __restrict__ out_m)
{
    extern __shared__ float sm[];
    float* sWt   = sm + SM_WT;
    float* szt   = sm + SM_ZT;
    float* svec  = sm + SM_VEC;
    int*   si    = (int*)(sm + SM_SI);
    int*   sj    = (int*)(sm + SM_SJ);

    const int tid = threadIdx.x;
    const int blk = blockIdx.x;
    const int b   = blk >> 7;

    // stage We2 transposed: sWt[j*76 + k] = We2[k*72 + j]
    for (int t = tid; t < 5184; t += 256) {
        int k = t / 72, j = t - k*72;
        sWt[j*76 + k] = We2[t];
    }
    if (tid < 72) {
        svec[tid]        = g_bn_e[tid];
        svec[72  + tid]  = g_bn_e[72 + tid];
        svec[144 + tid]  = We1[144*72 + tid];
        svec[216 + tid]  = We1[145*72 + tid];
        svec[288 + tid]  = be2[tid];
        svec[360 + tid]  = Wm[tid];
        svec[432 + tid]  = bx1[tid];
        svec[504 + tid]  = Wx2[tid];
    }
    if (tid < 128) {
        int eg = blk*128 + tid;
        si[tid] = ei[eg];
        sj[tid] = ej[eg];
    }
    float bmv = bm[0];
    __syncthreads();                                        // B1

    // phase A: zb = relu(BN(z1)) into szt (transposed), float4 gathers
    {
        int e = tid >> 1, half = tid & 1, c0 = half*36;
        int i = si[e], j = sj[e];
        const float* xi = x + (b*NN + i)*4;
        const float* xj = x + (b*NN + j)*4;
        float d0 = xi[0]-xj[0], d1 = xi[1]-xj[1], d2 = xi[2]-xj[2], d3 = xi[3]-xj[3];
        float nv = psi_f(d0*d0 - d1*d1 - d2*d2 - d3*d3);
        float dv = psi_f(xi[0]*xj[0] - xi[1]*xj[1] - xi[2]*xj[2] - xi[3]*xj[3]);
        const float4* Pr = (const float4*)(g_P + (size_t)(b*NN + i)*72 + c0);
        const float4* Qr = (const float4*)(g_Q + (size_t)(b*NN + j)*72 + c0);
        #pragma unroll
        for (int c4 = 0; c4 < 9; c4++) {
            float4 p = Pr[c4];
            float4 q = Qr[c4];
            int cc = c0 + c4*4;
            float v0 = p.x + q.x + nv*svec[144+cc+0] + dv*svec[216+cc+0];
            float v1 = p.y + q.y + nv*svec[144+cc+1] + dv*svec[216+cc+1];
            float v2 = p.z + q.z + nv*svec[144+cc+2] + dv*svec[216+cc+2];
            float v3 = p.w + q.w + nv*svec[144+cc+3] + dv*svec[216+cc+3];
            szt[(cc+0)*132 + e] = fmaxf(fmaf(v0, svec[cc+0], svec[72+cc+0]), 0.f);
            szt[(cc+1)*132 + e] = fmaxf(fmaf(v1, svec[cc+1], svec[72+cc+1]), 0.f);
            szt[(cc+2)*132 + e] = fmaxf(fmaf(v2, svec[cc+2], svec[72+cc+2]), 0.f);
            szt[(cc+3)*132 + e] = fmaxf(fmaf(v3, svec[cc+3], svec[72+cc+3]), 0.f);
        }
    }
    __syncthreads();                                        // B2

    const int egrp = tid >> 3;
    const int jo   = (tid & 7) * 9;
    const int e0   = egrp * 4;

    // phase B: GEMM1 (FFMA2, transposed float4 weight loads)
    unsigned long long a01[9], a23[9];
    #pragma unroll
    for (int jj = 0; jj < 9; jj++) {
        unsigned long long bv = pack2(svec[288 + jo + jj]);
        a01[jj] = bv; a23[jj] = bv;
    }
    #pragma unroll 2
    for (int k4 = 0; k4 < 72; k4 += 4) {
        ulonglong2 zp0 = *(const ulonglong2*)&szt[(k4+0)*132 + e0];
        ulonglong2 zp1 = *(const ulonglong2*)&szt[(k4+1)*132 + e0];
        ulonglong2 zp2 = *(const ulonglong2*)&szt[(k4+2)*132 + e0];
        ulonglong2 zp3 = *(const ulonglong2*)&szt[(k4+3)*132 + e0];
        #pragma unroll
        for (int jj = 0; jj < 9; jj++) {
            float4 w = *(const float4*)&sWt[(jo + jj)*76 + k4];
            unsigned long long w0 = pack2(w.x), w1 = pack2(w.y);
            unsigned long long w2 = pack2(w.z), w3 = pack2(w.w);
            fma2(a01[jj], zp0.x, w0); fma2(a23[jj], zp0.y, w0);
            fma2(a01[jj], zp1.x, w1); fma2(a23[jj], zp1.y, w1);
            fma2(a01[jj], zp2.x, w2); fma2(a23[jj], zp2.y, w2);
            fma2(a01[jj], zp3.x, w3); fma2(a23[jj], zp3.y, w3);
        }
    }
    float acc[36];
    #pragma unroll
    for (int jj = 0; jj < 9; jj++) {
        unpack2(a01[jj], acc[jj],    acc[9+jj]);
        unpack2(a23[jj], acc[18+jj], acc[27+jj]);
    }

    // phase C: relu + shuffle-reduced mdot over the 8-lane jo-group + sigmoid
    #pragma unroll
    for (int i = 0; i < 4; i++) {
        float pd = 0.f;
        #pragma unroll
        for (int jj = 0; jj < 9; jj++) {
            float v = fmaxf(acc[i*9 + jj], 0.f);
            acc[i*9 + jj] = v;
            pd = fmaf(v, svec[360 + jo + jj], pd);
        }
        pd += __shfl_xor_sync(0xffffffffu, pd, 1);
        pd += __shfl_xor_sync(0xffffffffu, pd, 2);
        pd += __shfl_xor_sync(0xffffffffu, pd, 4);
        float sg = 1.f / (1.f + expf(-(pd + bmv)));
        #pragma unroll
        for (int jj = 0; jj < 9; jj++) acc[i*9 + jj] *= sg;
    }
    __syncthreads();                                        // B3 (szt/sWt reads done)

    // phase D: m0 -> szt; restage sWt = Wx1^T
    #pragma unroll
    for (int jj = 0; jj < 9; jj++) {
        float4 v4 = make_float4(acc[jj], acc[9+jj], acc[18+jj], acc[27+jj]);
        *(float4*)&szt[(jo + jj)*132 + e0] = v4;
    }
    for (int t = tid; t < 5184; t += 256) {
        int k = t / 72, j = t - k*72;
        sWt[j*76 + k] = Wx1[t];
    }
    __syncthreads();                                        // B4

    // phase E: coalesced m output + vectorized magg reduction
    {
        float* mo = out_m + (size_t)blk * (128*72);
        int e  = tid & 127;
        int ch = tid >> 7;                 // 0 or 1
        float* ma = g_magg + (size_t)(b*NN + si[e])*72;
        #pragma unroll
        for (int s = 0; s < 9; s++) {
            int c0 = (ch + s*2) * 4;       // 0,8,..68 / 4,12,..71
            float v0 = szt[(c0+0)*132 + e];
            float v1 = szt[(c0+1)*132 + e];
            float v2 = szt[(c0+2)*132 + e];
            float v3 = szt[(c0+3)*132 + e];
            *(float4*)&mo[e*72 + c0] = make_float4(v0, v1, v2, v3);
            red_v4(ma + c0, v0, v1, v2, v3);
        }
    }

    // phase F: GEMM2 -> gate (shuffle-reduced), lane0 does x-path red.v4
    unsigned long long b01[9], b23[9];
    #pragma unroll
    for (int jj = 0; jj < 9; jj++) {
        unsigned long long bv = pack2(svec[432 + jo + jj]);
        b01[jj] = bv; b23[jj] = bv;
    }
    #pragma unroll 2
    for (int k4 = 0; k4 < 72; k4 += 4) {
        ulonglong2 zp0 = *(const ulonglong2*)&szt[(k4+0)*132 + e0];
        ulonglong2 zp1 = *(const ulonglong2*)&szt[(k4+1)*132 + e0];
        ulonglong2 zp2 = *(const ulonglong2*)&szt[(k4+2)*132 + e0];
        ulonglong2 zp3 = *(const ulonglong2*)&szt[(k4+3)*132 + e0];
        #pragma unroll
        for (int jj = 0; jj < 9; jj++) {
            float4 w = *(const float4*)&sWt[(jo + jj)*76 + k4];
            unsigned long long w0 = pack2(w.x), w1 = pack2(w.y);
            unsigned long long w2 = pack2(w.z), w3 = pack2(w.w);
            fma2(b01[jj], zp0.x, w0); fma2(b23[jj], zp0.y, w0);
            fma2(b01[jj], zp1.x, w1); fma2(b23[jj], zp1.y, w1);
            fma2(b01[jj], zp2.x, w2); fma2(b23[jj], zp2.y, w2);
            fma2(b01[jj], zp3.x, w3); fma2(b23[jj], zp3.y, w3);
        }
    }
    float pg[4];
    {
        float acc2[36];
        #pragma unroll
        for (int jj = 0; jj < 9; jj++) {
            unpack2(b01[jj], acc2[jj],    acc2[9+jj]);
            unpack2(b23[jj], acc2[18+jj], acc2[27+jj]);
        }
        #pragma unroll
        for (int i = 0; i < 4; i++) {
            float p = 0.f;
            #pragma unroll
            for (int jj = 0; jj < 9; jj++)
                p = fmaf(fmaxf(acc2[i*9 + jj], 0.f), svec[504 + jo + jj], p);
            p += __shfl_xor_sync(0xffffffffu, p, 1);
            p += __shfl_xor_sync(0xffffffffu, p, 2);
            p += __shfl_xor_sync(0xffffffffu, p, 4);
            pg[i] = p;
        }
    }
    if ((tid & 7) == 0) {
        #pragma unroll
        for (int i = 0; i < 4; i++) {
            int e = e0 + i;
            int ii = si[e], jn = sj[e];
            float4 xi = *(const float4*)(x + (b*NN + ii)*4);
            float4 xj = *(const float4*)(x + (b*NN + jn)*4);
            float g = pg[i];
            float t0 = fminf(fmaxf((xi.x - xj.x)*g, -100.f), 100.f);
            float t1 = fminf(fmaxf((xi.y - xj.y)*g, -100.f), 100.f);
            float t2 = fminf(fmaxf((xi.z - xj.z)*g, -100.f), 100.f);
            float t3 = fminf(fmaxf((xi.w - xj.w)*g, -100.f), 100.f);
            red_v4(g_agg + (size_t)(b*NN + ii)*4, t0, t1, t2, t3);
        }
    }
}

// ---- node MLP pre-BN: block GEMM (128 nodes/block, K=148) ----
__global__ void __launch_bounds__(256) k_node_h1(
    const float* __restrict__ h, const float* __restrict__ na,
    const float* __restrict__ Wh1, const float* __restrict__ bh1)
{
    extern __shared__ float smh[];
    float* sW    = smh;
    float* sin_t = smh + 10656;
    int tid = threadIdx.x;
    int blk = blockIdx.x;

    for (int t = tid; t < 10656; t += 256) sW[t] = Wh1[t];
    for (int idx = tid; idx < 148*128; idx += 256) {
        int k = idx >> 7, n = idx & 127;
        int bn = blk*128 + n;
        float v;
        if (k < 72)       v = h[bn*72 + k];
        else if (k < 144) v = g_magg[bn*72 + (k-72)];
        else              v = na[bn*4 + (k-144)];
        sin_t[k*132 + n] = v;
    }
    __syncthreads();

    const int egrp = tid >> 3;
    const int jo   = (tid & 7) * 9;
    const int e0   = egrp * 4;

    float acc[36];
    #pragma unroll
    for (int jj = 0; jj < 9; jj++) {
        float bv = __ldg(bh1 + jo + jj);
        acc[jj] = bv; acc[9+jj] = bv; acc[18+jj] = bv; acc[27+jj] = bv;
    }
    #pragma unroll 4
    for (int k = 0; k < 148; k++) {
        float4 zv = *(const float4*)&sin_t[k*132 + e0];
        #pragma unroll
        for (int jj = 0; jj < 9; jj++) {
            float w = sW[k*72 + jo + jj];
            acc[jj]    = fmaf(zv.x, w, acc[jj]);
            acc[9+jj]  = fmaf(zv.y, w, acc[9+jj]);
            acc[18+jj] = fmaf(zv.z, w, acc[18+jj]);
            acc[27+jj] = fmaf(zv.w, w, acc[27+jj]);
        }
    }
    #pragma unroll
    for (int i = 0; i < 4; i++) {
        float* zr = g_z2 + (size_t)(blk*128 + e0 + i)*72 + jo;
        #pragma unroll
        for (int jj = 0; jj < 9; jj++) zr[jj] = acc[i*9 + jj];
    }
}

__global__ void k_fin_h(const float* __restrict__ gh, const float* __restrict__ bh) {
    int c = blockIdx.x;
    int tid = threadIdx.x;
    double s = 0.0, q = 0.0;
    for (int r = tid; r < BN; r += 128) {
        double v = (double)g_z2[r*72 + c];
        s += v; q += v*v;
    }
    __shared__ double rs[128], rq[128];
    rs[tid] = s; rq[tid] = q;
    __syncthreads();
    for (int off = 64; off > 0; off >>= 1) {
        if (tid < off) { rs[tid] += rs[tid+off]; rq[tid] += rq[tid+off]; }
        __syncthreads();
    }
    if (tid == 0) {
        double mu = rs[0] / (double)BN;
        double var = rq[0] / (double)BN - mu*mu;
        float a = gh[c] * (float)(1.0 / sqrt(var + 1e-5));
        g_bn_h[c] = a;
        g_bn_h[72 + c] = bh[c] - (float)mu * a;
    }
}

// ---- node output: block GEMM (128 nodes/block, K=72) + x_out ----
__global__ void __launch_bounds__(256) k_node_h2(
    const float* __restrict__ h, const float* __restrict__ x,
    const float* __restrict__ Wh2, const float* __restrict__ bh2,
    float* __restrict__ out)
{
    extern __shared__ float smh[];
    float* sW   = smh;
    float* sv_t = smh + 5184;
    float* sbn  = smh + 14688;
    int tid = threadIdx.x;
    int blk = blockIdx.x;

    for (int t = tid; t < 5184; t += 256) sW[t] = Wh2[t];
    if (tid < 144) sbn[tid] = g_bn_h[tid];
    __syncthreads();
    for (int idx = tid; idx < 72*128; idx += 256) {
        int c = idx >> 7, n = idx & 127;
        float v = g_z2[(size_t)(blk*128 + n)*72 + c];
        sv_t[c*132 + n] = fmaxf(fmaf(v, sbn[c], sbn[72 + c]), 0.f);
    }
    __syncthreads();

    const int egrp = tid >> 3;
    const int jo   = (tid & 7) * 9;
    const int e0   = egrp * 4;

    float acc[36];
    #pragma unroll
    for (int jj = 0; jj < 9; jj++) {
        float bv = __ldg(bh2 + jo + jj);
        acc[jj] = bv; acc[9+jj] = bv; acc[18+jj] = bv; acc[27+jj] = bv;
    }
    #pragma unroll 4
    for (int k = 0; k < 72; k++) {
        float4 zv = *(const float4*)&sv_t[k*132 + e0];
        #pragma unroll
        for (int jj = 0; jj < 9; jj++) {
            float w = sW[k*72 + jo + jj];
            acc[jj]    = fmaf(zv.x, w, acc[jj]);
            acc[9+jj]  = fmaf(zv.y, w, acc[9+jj]);
            acc[18+jj] = fmaf(zv.z, w, acc[18+jj]);
            acc[27+jj] = fmaf(zv.w, w, acc[27+jj]);
        }
    }
    #pragma unroll
    for (int i = 0; i < 4; i++) {
        int bn = blk*128 + e0 + i;
        const float* hr = h + (size_t)bn*72 + jo;
        float* oh = out + (size_t)bn*72 + jo;
        #pragma unroll
        for (int jj = 0; jj < 9; jj++) oh[jj] = hr[jj] + acc[i*9 + jj];
    }

    if (tid < 128) {
        int bn = blk*128 + tid;
        float cn = fmaxf((float)g_cnt[bn], 1.f);
        float inv = 1.f / cn;
        float* ox = out + BN*HH + (size_t)bn*4;
        #pragma unroll
        for (int d = 0; d < 4; d++)
            ox[d] = x[bn*4 + d] + g_agg[bn*4 + d] * inv;
    }
}

extern "C" void kernel_launch(void* const* d_in, const int* in_sizes, int n_in,
                              void* d_out, int out_size)
{
    (void)in_sizes; (void)n_in; (void)out_size;
    const float* h   = (const float*)d_in[0];
    const float* x   = (const float*)d_in[1];
    const int*   ei  = (const int*)  d_in[2];
    const int*   ej  = (const int*)  d_in[3];
    const float* na  = (const float*)d_in[4];
    const float* We1 = (const float*)d_in[5];
    const float* g1  = (const float*)d_in[6];
    const float* b1  = (const float*)d_in[7];
    const float* We2 = (const float*)d_in[8];
    const float* be2 = (const float*)d_in[9];
    const float* Wm  = (const float*)d_in[10];
    const float* bm  = (const float*)d_in[11];
    const float* Wx1 = (const float*)d_in[12];
    const float* bx1 = (const float*)d_in[13];
    const float* Wx2 = (const float*)d_in[14];
    const float* Wh1 = (const float*)d_in[15];
    const float* bh1 = (const float*)d_in[16];
    const float* gh  = (const float*)d_in[17];
    const float* bhv = (const float*)d_in[18];
    const float* Wh2 = (const float*)d_in[19];
    const float* bh2 = (const float*)d_in[20];

    float* out = (float*)d_out;
    float* out_m = out + BN*HH + BN*4;

    cudaFuncSetAttribute(k_m, cudaFuncAttributeMaxDynamicSharedMemorySize,
                         SM_TOT * (int)sizeof(float));
    cudaFuncSetAttribute(k_node_h1, cudaFuncAttributeMaxDynamicSharedMemorySize,
                         30192 * (int)sizeof(float));
    cudaFuncSetAttribute(k_node_h2, cudaFuncAttributeMaxDynamicSharedMemorySize,
                         14832 * (int)sizeof(float));

    k_pre<<<BB, 128>>>(h, We1);                         // launch 1 (includes zeroing)
    k_stats<<<256, 288>>>(x, ei, ej, We1);              // launch 2
    k_fin_e<<<1, 72>>>(g1, b1);                         // launch 3
    k_m<<<ETOT/128, 256, SM_TOT*(int)sizeof(float)>>>(  // launch 4  <-- profile slot
        x, ei, ej, We1, We2, be2, Wm, bm, Wx1, bx1, Wx2, out_m);
    k_node_h1<<<BB, 256, 30192*(int)sizeof(float)>>>(h, na, Wh1, bh1);
    k_fin_h<<<72, 128>>>(gh, bhv);
    k_node_h2<<<BB, 256, 14832*(int)sizeof(float)>>>(h, x, Wh2, bh2, out);
}